// round 3
// baseline (speedup 1.0000x reference)
#include <cuda_runtime.h>
#include <math.h>
#include <stdint.h>

// Problem dims (fixed)
#define BB 2
#define SS 4096
#define DD 512

// Scratch (device globals: allocation-free rule)
__device__ float g_q[(size_t)BB * SS * DD];
__device__ float g_k[(size_t)BB * SS * DD];
__device__ float g_v[(size_t)BB * SS * DD];
__device__ float g_s[(size_t)BB * SS * SS];

// ---------------------------------------------------------------------------
// TF32 tensor-core GEMM: C = alpha * A * op(B)
//   TB=false: B is [K,N] row-major (NN)
//   TB=true : B is [N,K] row-major (NT)
// CTA tile 128x128x32, 256 threads (8 warps, 2x4), warp tile 64x32,
// mma.sync.aligned.m16n8k8.row.col.f32.tf32.tf32.f32.
// Padded (conflict-free, affine-address) smem layouts + double buffering.
// ---------------------------------------------------------------------------
#define BM 128
#define BN 128
#define BK 32
#define AW 36              // words per A (and NT-B) row: 32 + 4 pad
#define BWNN (BN + 8)      // words per NN-B row: 128 + 8 pad
#define ASZ (BM * AW)      // 4608 words

__device__ __forceinline__ uint32_t f2tf32(float f) {
    uint32_t r;
    asm("cvt.rna.tf32.f32 %0, %1;" : "=r"(r) : "f"(f));
    return r;
}

template <bool TB>
__global__ void __launch_bounds__(256, 2)
gemm_tf32(const float* __restrict__ A, const float* __restrict__ B,
          float* __restrict__ C, int K, int lda, int ldb, int ldc,
          long long sA, long long sB, long long sC, float alpha)
{
    extern __shared__ uint32_t sm[];
    const int BSZ = TB ? (BN * AW) : (BK * BWNN);
    const int STG = ASZ + BSZ;
    uint32_t* const AsBuf[2] = { sm,       sm + STG };
    uint32_t* const BsBuf[2] = { sm + ASZ, sm + STG + ASZ };

    A += (long long)blockIdx.z * sA;
    B += (long long)blockIdx.z * sB;
    C += (long long)blockIdx.z * sC;

    const int tid  = threadIdx.x;
    const int lane = tid & 31;
    const int wid  = tid >> 5;
    const int warp_m = wid >> 2;   // 0..1 -> 64-row slab
    const int warp_n = wid & 3;    // 0..3 -> 32-col slab
    const int g   = lane >> 2;     // 0..7
    const int tig = lane & 3;      // 0..3

    const int row0 = blockIdx.y * BM;
    const int col0 = blockIdx.x * BN;

    // Loader coords: 4 float4 per thread per operand tile
    int a_r[4], a_c[4], b_r[4], b_c[4];
#pragma unroll
    for (int i = 0; i < 4; i++) {
        int idx = tid + i * 256;
        a_r[i] = idx >> 3;            // m row
        a_c[i] = (idx & 7) * 4;       // k word
        if (TB) { b_r[i] = idx >> 3;  b_c[i] = (idx & 7) * 4; }   // n, k
        else    { b_r[i] = idx >> 5;  b_c[i] = (idx & 31) * 4; }  // k, n
    }

    float4 ra[4], rb[4];
    float acc[4][4][4];
#pragma unroll
    for (int mt = 0; mt < 4; mt++)
#pragma unroll
        for (int nt = 0; nt < 4; nt++)
#pragma unroll
            for (int i = 0; i < 4; i++) acc[mt][nt][i] = 0.0f;

    auto LOAD = [&](int k0) {
#pragma unroll
        for (int i = 0; i < 4; i++)
            ra[i] = *(const float4*)&A[(long long)(row0 + a_r[i]) * lda + k0 + a_c[i]];
#pragma unroll
        for (int i = 0; i < 4; i++) {
            if (TB)
                rb[i] = *(const float4*)&B[(long long)(col0 + b_r[i]) * ldb + k0 + b_c[i]];
            else
                rb[i] = *(const float4*)&B[(long long)(k0 + b_r[i]) * ldb + col0 + b_c[i]];
        }
    };

    auto STORE = [&](int s) {
        uint32_t* As = AsBuf[s];
        uint32_t* Bs = BsBuf[s];
#pragma unroll
        for (int i = 0; i < 4; i++) {
            uint4 u;
            u.x = f2tf32(ra[i].x); u.y = f2tf32(ra[i].y);
            u.z = f2tf32(ra[i].z); u.w = f2tf32(ra[i].w);
            *(uint4*)&As[a_r[i] * AW + a_c[i]] = u;
        }
#pragma unroll
        for (int i = 0; i < 4; i++) {
            uint4 u;
            u.x = f2tf32(rb[i].x); u.y = f2tf32(rb[i].y);
            u.z = f2tf32(rb[i].z); u.w = f2tf32(rb[i].w);
            if (TB)
                *(uint4*)&Bs[b_r[i] * AW + b_c[i]] = u;
            else
                *(uint4*)&Bs[b_r[i] * BWNN + b_c[i]] = u;
        }
    };

    auto COMPUTE = [&](int s) {
        const uint32_t* As = AsBuf[s];
        const uint32_t* Bs = BsBuf[s];
#pragma unroll
        for (int ks = 0; ks < 4; ks++) {
            const int kl = ks * 8;
            uint32_t af[4][4];
#pragma unroll
            for (int mt = 0; mt < 4; mt++) {
                const int m = warp_m * 64 + mt * 16;
                af[mt][0] = As[(m + g)     * AW + kl + tig];
                af[mt][1] = As[(m + g + 8) * AW + kl + tig];
                af[mt][2] = As[(m + g)     * AW + kl + tig + 4];
                af[mt][3] = As[(m + g + 8) * AW + kl + tig + 4];
            }
#pragma unroll
            for (int nt = 0; nt < 4; nt++) {
                const int nb = warp_n * 32 + nt * 8;
                uint32_t b0, b1;
                if (TB) {
                    b0 = Bs[(nb + g) * AW + kl + tig];
                    b1 = Bs[(nb + g) * AW + kl + tig + 4];
                } else {
                    b0 = Bs[(kl + tig)     * BWNN + nb + g];
                    b1 = Bs[(kl + tig + 4) * BWNN + nb + g];
                }
#pragma unroll
                for (int mt = 0; mt < 4; mt++) {
                    asm volatile(
                        "mma.sync.aligned.m16n8k8.row.col.f32.tf32.tf32.f32 "
                        "{%0,%1,%2,%3}, {%4,%5,%6,%7}, {%8,%9}, {%0,%1,%2,%3};"
                        : "+f"(acc[mt][nt][0]), "+f"(acc[mt][nt][1]),
                          "+f"(acc[mt][nt][2]), "+f"(acc[mt][nt][3])
                        : "r"(af[mt][0]), "r"(af[mt][1]),
                          "r"(af[mt][2]), "r"(af[mt][3]),
                          "r"(b0), "r"(b1));
                }
            }
        }
    };

    const int nT = K / BK;
    LOAD(0);
    STORE(0);
    __syncthreads();
    for (int t = 0; t < nT; t++) {
        if (t + 1 < nT) LOAD((t + 1) * BK);   // global prefetch overlaps MMA
        COMPUTE(t & 1);
        if (t + 1 < nT) {
            STORE((t + 1) & 1);
            __syncthreads();
        }
    }

    // Epilogue
#pragma unroll
    for (int mt = 0; mt < 4; mt++) {
        const int r = row0 + warp_m * 64 + mt * 16 + g;
#pragma unroll
        for (int nt = 0; nt < 4; nt++) {
            const int c = col0 + warp_n * 32 + nt * 8 + tig * 2;
            float2 v0, v1;
            v0.x = acc[mt][nt][0] * alpha; v0.y = acc[mt][nt][1] * alpha;
            v1.x = acc[mt][nt][2] * alpha; v1.y = acc[mt][nt][3] * alpha;
            *(float2*)&C[(long long)r * ldc + c]       = v0;
            *(float2*)&C[(long long)(r + 8) * ldc + c] = v1;
        }
    }
}

// ---------------------------------------------------------------------------
// Row softmax over n=4096 (one block of 256 threads per row; 16 values/thread)
// ---------------------------------------------------------------------------
__global__ void __launch_bounds__(256)
softmax_kernel(float* __restrict__ s)
{
    __shared__ float red[256];
    const long long row = blockIdx.x;
    float* p = s + row * (long long)SS;
    const int tid = threadIdx.x;

    float v[16];
    float mx = -1e30f;
#pragma unroll
    for (int i = 0; i < 16; i++) {
        v[i] = p[tid + i * 256];
        mx = fmaxf(mx, v[i]);
    }
    red[tid] = mx;
    __syncthreads();
    for (int w = 128; w > 0; w >>= 1) {
        if (tid < w) red[tid] = fmaxf(red[tid], red[tid + w]);
        __syncthreads();
    }
    mx = red[0];
    __syncthreads();

    float sum = 0.0f;
#pragma unroll
    for (int i = 0; i < 16; i++) {
        v[i] = __expf(v[i] - mx);
        sum += v[i];
    }
    red[tid] = sum;
    __syncthreads();
    for (int w = 128; w > 0; w >>= 1) {
        if (tid < w) red[tid] += red[tid + w];
        __syncthreads();
    }
    const float inv = 1.0f / red[0];
#pragma unroll
    for (int i = 0; i < 16; i++)
        p[tid + i * 256] = v[i] * inv;
}

// ---------------------------------------------------------------------------
extern "C" void kernel_launch(void* const* d_in, const int* in_sizes, int n_in,
                              void* d_out, int out_size)
{
    const float* x  = (const float*)d_in[0];
    const float* wq = (const float*)d_in[1];
    const float* wk = (const float*)d_in[2];
    const float* wv = (const float*)d_in[3];
    float* out = (float*)d_out;

    float *q, *k, *v, *s;
    cudaGetSymbolAddress((void**)&q, g_q);
    cudaGetSymbolAddress((void**)&k, g_k);
    cudaGetSymbolAddress((void**)&v, g_v);
    cudaGetSymbolAddress((void**)&s, g_s);

    const long long qkvStride = (long long)SS * DD;  // per-batch Q/K/V
    const long long sStride   = (long long)SS * SS;  // per-batch scores
    const float scale = 1.0f / sqrtf((float)DD);

    const int smemNN = (ASZ + BK * BWNN) * 2 * 4;    // 71680 B
    const int smemNT = (ASZ + BN * AW) * 2 * 4;      // 73728 B
    cudaFuncSetAttribute(gemm_tf32<false>,
                         cudaFuncAttributeMaxDynamicSharedMemorySize, smemNN);
    cudaFuncSetAttribute(gemm_tf32<true>,
                         cudaFuncAttributeMaxDynamicSharedMemorySize, smemNT);

    dim3 blk(256);

    // 1) QKV projections: [8192,512] x [512,512] (NN)
    {
        dim3 grid(DD / BN, (BB * SS) / BM, 1);
        gemm_tf32<false><<<grid, blk, smemNN>>>(x, wq, q, DD, DD, DD, DD, 0, 0, 0, 1.0f);
        gemm_tf32<false><<<grid, blk, smemNN>>>(x, wk, k, DD, DD, DD, DD, 0, 0, 0, 1.0f);
        gemm_tf32<false><<<grid, blk, smemNN>>>(x, wv, v, DD, DD, DD, DD, 0, 0, 0, 1.0f);
    }

    // 2) scores = scale * Q @ K^T  (NT), per batch
    {
        dim3 grid(SS / BN, SS / BM, BB);
        gemm_tf32<true><<<grid, blk, smemNT>>>(q, k, s, DD, DD, DD, SS,
                                               qkvStride, qkvStride, sStride, scale);
    }

    // 3) softmax rows
    {
        dim3 grid(BB * SS);
        softmax_kernel<<<grid, blk>>>(s);
    }

    // 4) context = P @ V  (NN), per batch
    {
        dim3 grid(DD / BN, SS / BM, BB);
        gemm_tf32<false><<<grid, blk, smemNN>>>(s, v, out, SS, SS, DD, DD,
                                                sStride, qkvStride, qkvStride, 1.0f);
    }
}

// round 8
// speedup vs baseline: 1.5440x; 1.5440x over previous
#include <cuda_runtime.h>
#include <math.h>
#include <stdint.h>

// Problem dims (fixed)
#define BB 2
#define SS 4096
#define DD 512

// Scratch (device globals: allocation-free rule)
__device__ float g_q[(size_t)BB * SS * DD];
__device__ float g_k[(size_t)BB * SS * DD];
__device__ float g_v[(size_t)BB * SS * DD];
__device__ float g_s[(size_t)BB * SS * SS];

// ---------------------------------------------------------------------------
// TF32 tensor-core GEMM: C = alpha * A * op(B)
//   TB=false: B is [K,N] row-major (NN)
//   TB=true : B is [N,K] row-major (NT)
// CTA tile 128x128x32, 256 threads (8 warps, 2x4), warp tile 64x32,
// mma.sync.aligned.m16n8k8.row.col.f32.tf32.tf32.f32.
// Round-2 structure (static smem, single buffer, reg prefetch) with
// padded-affine smem layouts (no XOR swizzle -> no ALU address math).
//   A / NT-B: [row][36 words] (32 k-words + 4 pad)  -> conflict-free
//   NN-B    : [k][BN+8]
// ---------------------------------------------------------------------------
#define BM 128
#define BN 128
#define BK 32
#define AW 36
#define BWNN (BN + 8)

__device__ __forceinline__ uint32_t f2tf32(float f) {
    uint32_t r;
    asm("cvt.rna.tf32.f32 %0, %1;" : "=r"(r) : "f"(f));
    return r;
}

template <bool TB>
__global__ void __launch_bounds__(256, 2)
gemm_tf32(const float* __restrict__ A, const float* __restrict__ B,
          float* __restrict__ C, int K, int lda, int ldb, int ldc,
          long long sA, long long sB, long long sC, float alpha)
{
    __shared__ uint32_t As[BM * AW];
    __shared__ uint32_t Bs[TB ? (BN * AW) : (BK * BWNN)];

    A += (long long)blockIdx.z * sA;
    B += (long long)blockIdx.z * sB;
    C += (long long)blockIdx.z * sC;

    const int tid  = threadIdx.x;
    const int lane = tid & 31;
    const int wid  = tid >> 5;
    const int warp_m = wid >> 2;   // 0..1 -> 64-row slab
    const int warp_n = wid & 3;    // 0..3 -> 32-col slab
    const int g   = lane >> 2;     // 0..7
    const int tig = lane & 3;      // 0..3

    const int row0 = blockIdx.y * BM;
    const int col0 = blockIdx.x * BN;

    // Loader coords: 4 float4 per thread per operand tile
    int a_r[4], a_c[4], b_r[4], b_c[4];
#pragma unroll
    for (int i = 0; i < 4; i++) {
        int idx = tid + i * 256;
        a_r[i] = idx >> 3;            // m row
        a_c[i] = (idx & 7) * 4;       // k word
        if (TB) { b_r[i] = idx >> 3;  b_c[i] = (idx & 7) * 4; }   // n, k
        else    { b_r[i] = idx >> 5;  b_c[i] = (idx & 31) * 4; }  // k, n
    }

    float4 ra[4], rb[4];
    float acc[4][4][4];
#pragma unroll
    for (int mt = 0; mt < 4; mt++)
#pragma unroll
        for (int nt = 0; nt < 4; nt++)
#pragma unroll
            for (int i = 0; i < 4; i++) acc[mt][nt][i] = 0.0f;

    auto LOAD = [&](int k0) {
#pragma unroll
        for (int i = 0; i < 4; i++)
            ra[i] = *(const float4*)&A[(long long)(row0 + a_r[i]) * lda + k0 + a_c[i]];
#pragma unroll
        for (int i = 0; i < 4; i++) {
            if (TB)
                rb[i] = *(const float4*)&B[(long long)(col0 + b_r[i]) * ldb + k0 + b_c[i]];
            else
                rb[i] = *(const float4*)&B[(long long)(k0 + b_r[i]) * ldb + col0 + b_c[i]];
        }
    };

    auto STORE = [&]() {
#pragma unroll
        for (int i = 0; i < 4; i++) {
            uint4 u;
            u.x = f2tf32(ra[i].x); u.y = f2tf32(ra[i].y);
            u.z = f2tf32(ra[i].z); u.w = f2tf32(ra[i].w);
            *(uint4*)&As[a_r[i] * AW + a_c[i]] = u;
        }
#pragma unroll
        for (int i = 0; i < 4; i++) {
            uint4 u;
            u.x = f2tf32(rb[i].x); u.y = f2tf32(rb[i].y);
            u.z = f2tf32(rb[i].z); u.w = f2tf32(rb[i].w);
            if (TB)
                *(uint4*)&Bs[b_r[i] * AW + b_c[i]] = u;
            else
                *(uint4*)&Bs[b_r[i] * BWNN + b_c[i]] = u;
        }
    };

    auto COMPUTE = [&]() {
#pragma unroll
        for (int ks = 0; ks < 4; ks++) {
            const int kl = ks * 8;
            uint32_t af[4][4];
#pragma unroll
            for (int mt = 0; mt < 4; mt++) {
                const int m = warp_m * 64 + mt * 16;
                af[mt][0] = As[(m + g)     * AW + kl + tig];
                af[mt][1] = As[(m + g + 8) * AW + kl + tig];
                af[mt][2] = As[(m + g)     * AW + kl + tig + 4];
                af[mt][3] = As[(m + g + 8) * AW + kl + tig + 4];
            }
#pragma unroll
            for (int nt = 0; nt < 4; nt++) {
                const int nb = warp_n * 32 + nt * 8;
                uint32_t b0, b1;
                if (TB) {
                    b0 = Bs[(nb + g) * AW + kl + tig];
                    b1 = Bs[(nb + g) * AW + kl + tig + 4];
                } else {
                    b0 = Bs[(kl + tig)     * BWNN + nb + g];
                    b1 = Bs[(kl + tig + 4) * BWNN + nb + g];
                }
#pragma unroll
                for (int mt = 0; mt < 4; mt++) {
                    asm volatile(
                        "mma.sync.aligned.m16n8k8.row.col.f32.tf32.tf32.f32 "
                        "{%0,%1,%2,%3}, {%4,%5,%6,%7}, {%8,%9}, {%0,%1,%2,%3};"
                        : "+f"(acc[mt][nt][0]), "+f"(acc[mt][nt][1]),
                          "+f"(acc[mt][nt][2]), "+f"(acc[mt][nt][3])
                        : "r"(af[mt][0]), "r"(af[mt][1]),
                          "r"(af[mt][2]), "r"(af[mt][3]),
                          "r"(b0), "r"(b1));
                }
            }
        }
    };

    const int nT = K / BK;
    LOAD(0);
    STORE();
    __syncthreads();
    for (int t = 1; t < nT; t++) {
        LOAD(t * BK);       // global prefetch overlaps compute below
        COMPUTE();
        __syncthreads();
        STORE();
        __syncthreads();
    }
    COMPUTE();

    // Epilogue
#pragma unroll
    for (int mt = 0; mt < 4; mt++) {
        const int r = row0 + warp_m * 64 + mt * 16 + g;
#pragma unroll
        for (int nt = 0; nt < 4; nt++) {
            const int c = col0 + warp_n * 32 + nt * 8 + tig * 2;
            float2 v0, v1;
            v0.x = acc[mt][nt][0] * alpha; v0.y = acc[mt][nt][1] * alpha;
            v1.x = acc[mt][nt][2] * alpha; v1.y = acc[mt][nt][3] * alpha;
            *(float2*)&C[(long long)r * ldc + c]       = v0;
            *(float2*)&C[(long long)(r + 8) * ldc + c] = v1;
        }
    }
}

// ---------------------------------------------------------------------------
// Row softmax over n=4096 (one block of 256 threads per row; 16 values/thread)
// ---------------------------------------------------------------------------
__global__ void __launch_bounds__(256)
softmax_kernel(float* __restrict__ s)
{
    __shared__ float red[256];
    const long long row = blockIdx.x;
    float* p = s + row * (long long)SS;
    const int tid = threadIdx.x;

    float v[16];
    float mx = -1e30f;
#pragma unroll
    for (int i = 0; i < 16; i++) {
        v[i] = p[tid + i * 256];
        mx = fmaxf(mx, v[i]);
    }
    red[tid] = mx;
    __syncthreads();
    for (int w = 128; w > 0; w >>= 1) {
        if (tid < w) red[tid] = fmaxf(red[tid], red[tid + w]);
        __syncthreads();
    }
    mx = red[0];
    __syncthreads();

    float sum = 0.0f;
#pragma unroll
    for (int i = 0; i < 16; i++) {
        v[i] = __expf(v[i] - mx);
        sum += v[i];
    }
    red[tid] = sum;
    __syncthreads();
    for (int w = 128; w > 0; w >>= 1) {
        if (tid < w) red[tid] += red[tid + w];
        __syncthreads();
    }
    const float inv = 1.0f / red[0];
#pragma unroll
    for (int i = 0; i < 16; i++)
        p[tid + i * 256] = v[i] * inv;
}

// ---------------------------------------------------------------------------
extern "C" void kernel_launch(void* const* d_in, const int* in_sizes, int n_in,
                              void* d_out, int out_size)
{
    const float* x  = (const float*)d_in[0];
    const float* wq = (const float*)d_in[1];
    const float* wk = (const float*)d_in[2];
    const float* wv = (const float*)d_in[3];
    float* out = (float*)d_out;

    float *q, *k, *v, *s;
    cudaGetSymbolAddress((void**)&q, g_q);
    cudaGetSymbolAddress((void**)&k, g_k);
    cudaGetSymbolAddress((void**)&v, g_v);
    cudaGetSymbolAddress((void**)&s, g_s);

    const long long qkvStride = (long long)SS * DD;  // per-batch Q/K/V
    const long long sStride   = (long long)SS * SS;  // per-batch scores
    const float scale = 1.0f / sqrtf((float)DD);

    dim3 blk(256);

    // 1) QKV projections: [8192,512] x [512,512] (NN)
    {
        dim3 grid(DD / BN, (BB * SS) / BM, 1);
        gemm_tf32<false><<<grid, blk>>>(x, wq, q, DD, DD, DD, DD, 0, 0, 0, 1.0f);
        gemm_tf32<false><<<grid, blk>>>(x, wk, k, DD, DD, DD, DD, 0, 0, 0, 1.0f);
        gemm_tf32<false><<<grid, blk>>>(x, wv, v, DD, DD, DD, DD, 0, 0, 0, 1.0f);
    }

    // 2) scores = scale * Q @ K^T  (NT), per batch
    {
        dim3 grid(SS / BN, SS / BM, BB);
        gemm_tf32<true><<<grid, blk>>>(q, k, s, DD, DD, DD, SS,
                                       qkvStride, qkvStride, sStride, scale);
    }

    // 3) softmax rows
    {
        dim3 grid(BB * SS);
        softmax_kernel<<<grid, blk>>>(s);
    }

    // 4) context = P @ V  (NN), per batch  — A = scores, lda = SS (4096)!
    {
        dim3 grid(DD / BN, SS / BM, BB);
        gemm_tf32<false><<<grid, blk>>>(s, v, out, SS, SS, DD, DD,
                                        sStride, qkvStride, qkvStride, 1.0f);
    }
}

// round 10
// speedup vs baseline: 1.8970x; 1.2286x over previous
#include <cuda_runtime.h>
#include <cuda_fp16.h>
#include <math.h>
#include <stdint.h>

// Problem dims (fixed)
#define BB 2
#define SS 4096
#define DD 512

// Scratch (device globals: allocation-free rule)
__device__ float g_q[(size_t)BB * SS * DD];
__device__ float g_k[(size_t)BB * SS * DD];
__device__ float g_v[(size_t)BB * SS * DD];
__device__ float g_s[(size_t)BB * SS * SS];

// ---------------------------------------------------------------------------
// FP16 tensor-core GEMM (fp32 in/out, fp16 multiply, fp32 accumulate):
//   C = alpha * A * op(B)
//   TB=false: B is [K,N] row-major (NN)
//   TB=true : B is [N,K] row-major (NT)
// CTA tile 128x128x32, 256 threads (8 warps, 2x4), warp tile 64x32,
// mma.sync.aligned.m16n8k16.row.col.f32.f16.f16.f32.
// fp16 has the same 10-bit mantissa as tf32 -> same error class, 2x rate,
// half the smem/L1 bytes (the round-8 bottleneck).
// Smem tiles hold half2 words:
//   A / NT-B: [row][20 words]  (16 data + 4 pad; fragment LDS conflict-free:
//             banks g*20+tig mod 32 all distinct)
//   NN-B    : [kw][136 words]  (16 k-pair rows; banks 8*tig+g all distinct)
// ---------------------------------------------------------------------------
#define BM 128
#define BN 128
#define BK 32              // k-depth per tile in fp32 elements (= 16 words)
#define AW 20              // words per A / NT-B row
#define BWNN (BN + 8)      // words per NN-B row

__device__ __forceinline__ uint32_t pack2(float lo, float hi) {
    __half2 h = __floats2half2_rn(lo, hi);   // .x = lo (bits 15:0)
    return *(uint32_t*)&h;
}

template <bool TB>
__global__ void __launch_bounds__(256, 2)
gemm_f16(const float* __restrict__ A, const float* __restrict__ B,
         float* __restrict__ C, int K, int lda, int ldb, int ldc,
         long long sA, long long sB, long long sC, float alpha)
{
    __shared__ uint32_t As[BM * AW];                       // 10240 B
    __shared__ uint32_t Bs[TB ? (BN * AW) : (16 * BWNN)];  // 10240 / 8704 B

    A += (long long)blockIdx.z * sA;
    B += (long long)blockIdx.z * sB;
    C += (long long)blockIdx.z * sC;

    const int tid  = threadIdx.x;
    const int lane = tid & 31;
    const int wid  = tid >> 5;
    const int warp_m = wid >> 2;   // 0..1 -> 64-row slab
    const int warp_n = wid & 3;    // 0..3 -> 32-col slab
    const int g   = lane >> 2;     // 0..7
    const int tig = lane & 3;      // 0..3

    const int row0 = blockIdx.y * BM;
    const int col0 = blockIdx.x * BN;

    // Loader coords.
    // A (and NT-B): 4 tasks; task -> row (idx>>3), float col (idx&7)*4,
    //               word col (idx&7)*2.
    int a_r[4], a_cf[4], a_cw[4];
#pragma unroll
    for (int i = 0; i < 4; i++) {
        int idx = tid + i * 256;
        a_r[i]  = idx >> 3;
        a_cf[i] = (idx & 7) * 4;
        a_cw[i] = (idx & 7) * 2;
    }
    // NN-B: 2 tasks; task -> k-pair row j (idx>>5), word col n4 (idx&31)*4.
    int b_j[2], b_n4[2];
#pragma unroll
    for (int i = 0; i < 2; i++) {
        int idx = tid + i * 256;
        b_j[i]  = idx >> 5;
        b_n4[i] = (idx & 31) * 4;
    }

    float4 ra[4], rb[4];
    float acc[4][4][4];
#pragma unroll
    for (int mt = 0; mt < 4; mt++)
#pragma unroll
        for (int nt = 0; nt < 4; nt++)
#pragma unroll
            for (int i = 0; i < 4; i++) acc[mt][nt][i] = 0.0f;

    auto LOAD = [&](int k0) {
#pragma unroll
        for (int i = 0; i < 4; i++)
            ra[i] = *(const float4*)&A[(long long)(row0 + a_r[i]) * lda + k0 + a_cf[i]];
        if (TB) {
#pragma unroll
            for (int i = 0; i < 4; i++)
                rb[i] = *(const float4*)&B[(long long)(col0 + a_r[i]) * ldb + k0 + a_cf[i]];
        } else {
#pragma unroll
            for (int i = 0; i < 2; i++) {
                rb[2*i]   = *(const float4*)&B[(long long)(k0 + 2*b_j[i])     * ldb + col0 + b_n4[i]];
                rb[2*i+1] = *(const float4*)&B[(long long)(k0 + 2*b_j[i] + 1) * ldb + col0 + b_n4[i]];
            }
        }
    };

    auto STORE = [&]() {
#pragma unroll
        for (int i = 0; i < 4; i++) {
            uint2 w;
            w.x = pack2(ra[i].x, ra[i].y);
            w.y = pack2(ra[i].z, ra[i].w);
            *(uint2*)&As[a_r[i] * AW + a_cw[i]] = w;
        }
        if (TB) {
#pragma unroll
            for (int i = 0; i < 4; i++) {
                uint2 w;
                w.x = pack2(rb[i].x, rb[i].y);
                w.y = pack2(rb[i].z, rb[i].w);
                *(uint2*)&Bs[a_r[i] * AW + a_cw[i]] = w;
            }
        } else {
#pragma unroll
            for (int i = 0; i < 2; i++) {
                uint4 w;   // word n holds {B[2j][n], B[2j+1][n]}
                w.x = pack2(rb[2*i].x, rb[2*i+1].x);
                w.y = pack2(rb[2*i].y, rb[2*i+1].y);
                w.z = pack2(rb[2*i].z, rb[2*i+1].z);
                w.w = pack2(rb[2*i].w, rb[2*i+1].w);
                *(uint4*)&Bs[b_j[i] * BWNN + b_n4[i]] = w;
            }
        }
    };

    auto COMPUTE = [&]() {
#pragma unroll
        for (int s = 0; s < 2; s++) {          // two k16 steps per tile
            const int c0 = s * 8;
            uint32_t af[4][4];
#pragma unroll
            for (int mt = 0; mt < 4; mt++) {
                const int m = warp_m * 64 + mt * 16;
                af[mt][0] = As[(m + g)     * AW + c0 + tig];
                af[mt][1] = As[(m + g + 8) * AW + c0 + tig];
                af[mt][2] = As[(m + g)     * AW + c0 + tig + 4];
                af[mt][3] = As[(m + g + 8) * AW + c0 + tig + 4];
            }
#pragma unroll
            for (int nt = 0; nt < 4; nt++) {
                const int nb = warp_n * 32 + nt * 8;
                uint32_t b0, b1;
                if (TB) {
                    b0 = Bs[(nb + g) * AW + c0 + tig];
                    b1 = Bs[(nb + g) * AW + c0 + tig + 4];
                } else {
                    b0 = Bs[(c0 + tig)     * BWNN + nb + g];
                    b1 = Bs[(c0 + tig + 4) * BWNN + nb + g];
                }
#pragma unroll
                for (int mt = 0; mt < 4; mt++) {
                    asm volatile(
                        "mma.sync.aligned.m16n8k16.row.col.f32.f16.f16.f32 "
                        "{%0,%1,%2,%3}, {%4,%5,%6,%7}, {%8,%9}, {%0,%1,%2,%3};"
                        : "+f"(acc[mt][nt][0]), "+f"(acc[mt][nt][1]),
                          "+f"(acc[mt][nt][2]), "+f"(acc[mt][nt][3])
                        : "r"(af[mt][0]), "r"(af[mt][1]),
                          "r"(af[mt][2]), "r"(af[mt][3]),
                          "r"(b0), "r"(b1));
                }
            }
        }
    };

    const int nT = K / BK;
    LOAD(0);
    STORE();
    __syncthreads();
    for (int t = 1; t < nT; t++) {
        LOAD(t * BK);       // global prefetch overlaps compute below
        COMPUTE();
        __syncthreads();
        STORE();
        __syncthreads();
    }
    COMPUTE();

    // Epilogue
#pragma unroll
    for (int mt = 0; mt < 4; mt++) {
        const int r = row0 + warp_m * 64 + mt * 16 + g;
#pragma unroll
        for (int nt = 0; nt < 4; nt++) {
            const int c = col0 + warp_n * 32 + nt * 8 + tig * 2;
            float2 v0, v1;
            v0.x = acc[mt][nt][0] * alpha; v0.y = acc[mt][nt][1] * alpha;
            v1.x = acc[mt][nt][2] * alpha; v1.y = acc[mt][nt][3] * alpha;
            *(float2*)&C[(long long)r * ldc + c]       = v0;
            *(float2*)&C[(long long)(r + 8) * ldc + c] = v1;
        }
    }
}

// ---------------------------------------------------------------------------
// Row softmax over n=4096 (one block of 256 threads per row; 16 values/thread)
// ---------------------------------------------------------------------------
__global__ void __launch_bounds__(256)
softmax_kernel(float* __restrict__ s)
{
    __shared__ float red[256];
    const long long row = blockIdx.x;
    float* p = s + row * (long long)SS;
    const int tid = threadIdx.x;

    float v[16];
    float mx = -1e30f;
#pragma unroll
    for (int i = 0; i < 16; i++) {
        v[i] = p[tid + i * 256];
        mx = fmaxf(mx, v[i]);
    }
    red[tid] = mx;
    __syncthreads();
    for (int w = 128; w > 0; w >>= 1) {
        if (tid < w) red[tid] = fmaxf(red[tid], red[tid + w]);
        __syncthreads();
    }
    mx = red[0];
    __syncthreads();

    float sum = 0.0f;
#pragma unroll
    for (int i = 0; i < 16; i++) {
        v[i] = __expf(v[i] - mx);
        sum += v[i];
    }
    red[tid] = sum;
    __syncthreads();
    for (int w = 128; w > 0; w >>= 1) {
        if (tid < w) red[tid] += red[tid + w];
        __syncthreads();
    }
    const float inv = 1.0f / red[0];
#pragma unroll
    for (int i = 0; i < 16; i++)
        p[tid + i * 256] = v[i] * inv;
}

// ---------------------------------------------------------------------------
extern "C" void kernel_launch(void* const* d_in, const int* in_sizes, int n_in,
                              void* d_out, int out_size)
{
    const float* x  = (const float*)d_in[0];
    const float* wq = (const float*)d_in[1];
    const float* wk = (const float*)d_in[2];
    const float* wv = (const float*)d_in[3];
    float* out = (float*)d_out;

    float *q, *k, *v, *s;
    cudaGetSymbolAddress((void**)&q, g_q);
    cudaGetSymbolAddress((void**)&k, g_k);
    cudaGetSymbolAddress((void**)&v, g_v);
    cudaGetSymbolAddress((void**)&s, g_s);

    const long long qkvStride = (long long)SS * DD;  // per-batch Q/K/V
    const long long sStride   = (long long)SS * SS;  // per-batch scores
    const float scale = 1.0f / sqrtf((float)DD);

    dim3 blk(256);

    // 1) QKV projections: [8192,512] x [512,512] (NN)
    {
        dim3 grid(DD / BN, (BB * SS) / BM, 1);
        gemm_f16<false><<<grid, blk>>>(x, wq, q, DD, DD, DD, DD, 0, 0, 0, 1.0f);
        gemm_f16<false><<<grid, blk>>>(x, wk, k, DD, DD, DD, DD, 0, 0, 0, 1.0f);
        gemm_f16<false><<<grid, blk>>>(x, wv, v, DD, DD, DD, DD, 0, 0, 0, 1.0f);
    }

    // 2) scores = scale * Q @ K^T  (NT), per batch
    {
        dim3 grid(SS / BN, SS / BM, BB);
        gemm_f16<true><<<grid, blk>>>(q, k, s, DD, DD, DD, SS,
                                      qkvStride, qkvStride, sStride, scale);
    }

    // 3) softmax rows
    {
        dim3 grid(BB * SS);
        softmax_kernel<<<grid, blk>>>(s);
    }

    // 4) context = P @ V  (NN), per batch  (A = scores, lda = SS)
    {
        dim3 grid(DD / BN, SS / BM, BB);
        gemm_f16<false><<<grid, blk>>>(s, v, out, SS, SS, DD, DD,
                                       sStride, qkvStride, qkvStride, 1.0f);
    }
}

// round 11
// speedup vs baseline: 2.6074x; 1.3745x over previous
#include <cuda_runtime.h>
#include <cuda_fp16.h>
#include <math.h>
#include <stdint.h>

// Problem dims (fixed)
#define BB 2
#define SS 4096
#define DD 512

// Scratch (device globals: allocation-free rule)
__device__ __align__(256) __half g_qh[(size_t)BB * SS * DD];   // Q [b][s][d] fp16
__device__ __align__(256) __half g_kh[(size_t)BB * SS * DD];   // K [b][s][d] fp16
__device__ __align__(256) __half g_vt[(size_t)BB * DD * SS];   // V^T [b][d][s] fp16
__device__ __align__(256) float  g_s [(size_t)BB * SS * SS];   // scores fp32
__device__ __align__(256) __half g_p [(size_t)BB * SS * SS];   // softmax(P) fp16

__device__ __forceinline__ uint32_t pack2(float lo, float hi) {
    __half2 h = __floats2half2_rn(lo, hi);
    return *(uint32_t*)&h;
}

// ===========================================================================
// NT fp16-operand GEMM: C(fp32) = alpha * A * B^T
//   A [M,K] row-major fp16 (lda), B [N,K] row-major fp16 (ldb)
// CTA 128x128x32(halves), 128 threads = 4 warps (2x2), warp tile 64x64,
// mma.sync.m16n8k16.f32.f16.f16.f32.
// Smem: 16 words (half2) per row, 16B-chunk XOR swizzle, key = (row>>1)&3.
// Fragment loads use 4 precomputed xored chunk-base registers -> every
// mainloop LDS is [reg + immediate], zero ALU, conflict-free.
// ===========================================================================
__global__ void __launch_bounds__(128, 2)
gemm_h_nt(const __half* __restrict__ A, const __half* __restrict__ B,
          float* __restrict__ C, int K, int lda, int ldb, int ldc,
          long long sA, long long sB, long long sC, float alpha)
{
    __shared__ uint32_t As[128 * 16];   // 8 KB
    __shared__ uint32_t Bs[128 * 16];   // 8 KB

    A += (long long)blockIdx.z * sA;
    B += (long long)blockIdx.z * sB;
    C += (long long)blockIdx.z * sC;

    const int tid  = threadIdx.x;
    const int lane = tid & 31;
    const int wid  = tid >> 5;
    const int warp_m = wid >> 1;          // 0..1 -> 64-row slab
    const int warp_n = wid & 1;           // 0..1 -> 64-col slab
    const int g   = lane >> 2;            // 0..7
    const int tig = lane & 3;             // 0..3

    const int row0 = blockIdx.y * 128;
    const int col0 = blockIdx.x * 128;

    // Loader: 4 tasks/operand; task -> tile row (idx>>2), 16B chunk (idx&3)
    int l_r[4], l_c[4], st_off[4];
#pragma unroll
    for (int i = 0; i < 4; i++) {
        int idx = tid + i * 128;
        l_r[i] = idx >> 2;
        l_c[i] = idx & 3;
        st_off[i] = l_r[i] * 16 + ((l_c[i] ^ ((l_r[i] >> 1) & 3)) << 2);
    }

    // Fragment chunk-base word offsets (xor key invariant across mt/nt)
    const int lc = (g >> 1) & 3;
    int fa[4], fb[4];
#pragma unroll
    for (int c = 0; c < 4; c++) {
        fa[c] = (warp_m * 64 + g) * 16 + ((c ^ lc) << 2) + tig;
        fb[c] = (warp_n * 64 + g) * 16 + ((c ^ lc) << 2) + tig;
    }

    uint4 ra[4], rb[4];
    float acc[4][8][4];
#pragma unroll
    for (int mt = 0; mt < 4; mt++)
#pragma unroll
        for (int nt = 0; nt < 8; nt++)
#pragma unroll
            for (int i = 0; i < 4; i++) acc[mt][nt][i] = 0.0f;

    auto LOAD = [&](int k0) {
#pragma unroll
        for (int i = 0; i < 4; i++)
            ra[i] = *(const uint4*)&A[(long long)(row0 + l_r[i]) * lda + k0 + l_c[i] * 8];
#pragma unroll
        for (int i = 0; i < 4; i++)
            rb[i] = *(const uint4*)&B[(long long)(col0 + l_r[i]) * ldb + k0 + l_c[i] * 8];
    };
    auto STORE = [&]() {
#pragma unroll
        for (int i = 0; i < 4; i++) *(uint4*)&As[st_off[i]] = ra[i];
#pragma unroll
        for (int i = 0; i < 4; i++) *(uint4*)&Bs[st_off[i]] = rb[i];
    };

    auto COMPUTE = [&]() {
#pragma unroll
        for (int s = 0; s < 2; s++) {
            uint32_t af[4][4], bf[8][2];
#pragma unroll
            for (int mt = 0; mt < 4; mt++) {
                af[mt][0] = As[fa[2*s]     + mt * 256];
                af[mt][1] = As[fa[2*s]     + mt * 256 + 128];
                af[mt][2] = As[fa[2*s + 1] + mt * 256];
                af[mt][3] = As[fa[2*s + 1] + mt * 256 + 128];
            }
#pragma unroll
            for (int nt = 0; nt < 8; nt++) {
                bf[nt][0] = Bs[fb[2*s]     + nt * 128];
                bf[nt][1] = Bs[fb[2*s + 1] + nt * 128];
            }
#pragma unroll
            for (int nt = 0; nt < 8; nt++)
#pragma unroll
                for (int mt = 0; mt < 4; mt++) {
                    asm volatile(
                        "mma.sync.aligned.m16n8k16.row.col.f32.f16.f16.f32 "
                        "{%0,%1,%2,%3}, {%4,%5,%6,%7}, {%8,%9}, {%0,%1,%2,%3};"
                        : "+f"(acc[mt][nt][0]), "+f"(acc[mt][nt][1]),
                          "+f"(acc[mt][nt][2]), "+f"(acc[mt][nt][3])
                        : "r"(af[mt][0]), "r"(af[mt][1]),
                          "r"(af[mt][2]), "r"(af[mt][3]),
                          "r"(bf[nt][0]), "r"(bf[nt][1]));
                }
        }
    };

    const int nT = K / 32;
    LOAD(0);
    STORE();
    __syncthreads();
    for (int t = 1; t < nT; t++) {
        LOAD(t * 32);
        COMPUTE();
        __syncthreads();
        STORE();
        __syncthreads();
    }
    COMPUTE();

    // Epilogue (fp32)
#pragma unroll
    for (int mt = 0; mt < 4; mt++) {
        const int r = row0 + warp_m * 64 + mt * 16 + g;
#pragma unroll
        for (int nt = 0; nt < 8; nt++) {
            const int c = col0 + warp_n * 64 + nt * 8 + tig * 2;
            float2 v0, v1;
            v0.x = acc[mt][nt][0] * alpha; v0.y = acc[mt][nt][1] * alpha;
            v1.x = acc[mt][nt][2] * alpha; v1.y = acc[mt][nt][3] * alpha;
            *(float2*)&C[(long long)r * ldc + c]       = v0;
            *(float2*)&C[(long long)(r + 8) * ldc + c] = v1;
        }
    }
}

// ===========================================================================
// Projection GEMM (fp32 in, fp16 out): C = A[8192,512] @ B[512,512]
// Round-10 proven structure (256 thr, 2x4 warps of 64x32, NN).
//   OMODE 0: C half [r][c] (ldc=DD)
//   OMODE 1: C half transposed per batch: vt[b][c][s]
// ===========================================================================
#define AW 20
#define BWNN 136

template <int OMODE>
__global__ void __launch_bounds__(256, 2)
gemm_proj(const float* __restrict__ A, const float* __restrict__ B,
          __half* __restrict__ C)
{
    __shared__ uint32_t As[128 * AW];
    __shared__ uint32_t Bs[16 * BWNN];

    const int tid  = threadIdx.x;
    const int lane = tid & 31;
    const int wid  = tid >> 5;
    const int warp_m = wid >> 2;
    const int warp_n = wid & 3;
    const int g   = lane >> 2;
    const int tig = lane & 3;
    const int row0 = blockIdx.y * 128;
    const int col0 = blockIdx.x * 128;

    int a_r[4], a_cf[4], a_cw[4];
#pragma unroll
    for (int i = 0; i < 4; i++) {
        int idx = tid + i * 256;
        a_r[i]  = idx >> 3;
        a_cf[i] = (idx & 7) * 4;
        a_cw[i] = (idx & 7) * 2;
    }
    int b_j[2], b_n4[2];
#pragma unroll
    for (int i = 0; i < 2; i++) {
        int idx = tid + i * 256;
        b_j[i]  = idx >> 5;
        b_n4[i] = (idx & 31) * 4;
    }

    float4 ra[4], rb[4];
    float acc[4][4][4];
#pragma unroll
    for (int mt = 0; mt < 4; mt++)
#pragma unroll
        for (int nt = 0; nt < 4; nt++)
#pragma unroll
            for (int i = 0; i < 4; i++) acc[mt][nt][i] = 0.0f;

    auto LOAD = [&](int k0) {
#pragma unroll
        for (int i = 0; i < 4; i++)
            ra[i] = *(const float4*)&A[(long long)(row0 + a_r[i]) * DD + k0 + a_cf[i]];
#pragma unroll
        for (int i = 0; i < 2; i++) {
            rb[2*i]   = *(const float4*)&B[(long long)(k0 + 2*b_j[i])     * DD + col0 + b_n4[i]];
            rb[2*i+1] = *(const float4*)&B[(long long)(k0 + 2*b_j[i] + 1) * DD + col0 + b_n4[i]];
        }
    };
    auto STORE = [&]() {
#pragma unroll
        for (int i = 0; i < 4; i++) {
            uint2 w;
            w.x = pack2(ra[i].x, ra[i].y);
            w.y = pack2(ra[i].z, ra[i].w);
            *(uint2*)&As[a_r[i] * AW + a_cw[i]] = w;
        }
#pragma unroll
        for (int i = 0; i < 2; i++) {
            uint4 w;
            w.x = pack2(rb[2*i].x, rb[2*i+1].x);
            w.y = pack2(rb[2*i].y, rb[2*i+1].y);
            w.z = pack2(rb[2*i].z, rb[2*i+1].z);
            w.w = pack2(rb[2*i].w, rb[2*i+1].w);
            *(uint4*)&Bs[b_j[i] * BWNN + b_n4[i]] = w;
        }
    };
    auto COMPUTE = [&]() {
#pragma unroll
        for (int s = 0; s < 2; s++) {
            const int c0 = s * 8;
            uint32_t af[4][4];
#pragma unroll
            for (int mt = 0; mt < 4; mt++) {
                const int m = warp_m * 64 + mt * 16;
                af[mt][0] = As[(m + g)     * AW + c0 + tig];
                af[mt][1] = As[(m + g + 8) * AW + c0 + tig];
                af[mt][2] = As[(m + g)     * AW + c0 + tig + 4];
                af[mt][3] = As[(m + g + 8) * AW + c0 + tig + 4];
            }
#pragma unroll
            for (int nt = 0; nt < 4; nt++) {
                const int nb = warp_n * 32 + nt * 8;
                uint32_t b0 = Bs[(c0 + tig)     * BWNN + nb + g];
                uint32_t b1 = Bs[(c0 + tig + 4) * BWNN + nb + g];
#pragma unroll
                for (int mt = 0; mt < 4; mt++) {
                    asm volatile(
                        "mma.sync.aligned.m16n8k16.row.col.f32.f16.f16.f32 "
                        "{%0,%1,%2,%3}, {%4,%5,%6,%7}, {%8,%9}, {%0,%1,%2,%3};"
                        : "+f"(acc[mt][nt][0]), "+f"(acc[mt][nt][1]),
                          "+f"(acc[mt][nt][2]), "+f"(acc[mt][nt][3])
                        : "r"(af[mt][0]), "r"(af[mt][1]),
                          "r"(af[mt][2]), "r"(af[mt][3]),
                          "r"(b0), "r"(b1));
                }
            }
        }
    };

    const int nT = DD / 32;
    LOAD(0);
    STORE();
    __syncthreads();
    for (int t = 1; t < nT; t++) {
        LOAD(t * 32);
        COMPUTE();
        __syncthreads();
        STORE();
        __syncthreads();
    }
    COMPUTE();

#pragma unroll
    for (int mt = 0; mt < 4; mt++) {
        const int r = row0 + warp_m * 64 + mt * 16 + g;
#pragma unroll
        for (int nt = 0; nt < 4; nt++) {
            const int c = col0 + warp_n * 32 + nt * 8 + tig * 2;
            if (OMODE == 0) {
                *(__half2*)&C[(long long)r * DD + c] =
                    __floats2half2_rn(acc[mt][nt][0], acc[mt][nt][1]);
                *(__half2*)&C[(long long)(r + 8) * DD + c] =
                    __floats2half2_rn(acc[mt][nt][2], acc[mt][nt][3]);
            } else {
                const int b  = r >> 12;
                const int sr = r & (SS - 1);
                __half* base = C + (long long)b * DD * SS;
                base[(long long)(c)     * SS + sr]     = __float2half_rn(acc[mt][nt][0]);
                base[(long long)(c + 1) * SS + sr]     = __float2half_rn(acc[mt][nt][1]);
                base[(long long)(c)     * SS + sr + 8] = __float2half_rn(acc[mt][nt][2]);
                base[(long long)(c + 1) * SS + sr + 8] = __float2half_rn(acc[mt][nt][3]);
            }
        }
    }
}

// ---------------------------------------------------------------------------
// Row softmax: fp32 scores in, fp16 P out. 16 consecutive elems per thread.
// ---------------------------------------------------------------------------
__global__ void __launch_bounds__(256)
softmax_h(const float* __restrict__ s, __half* __restrict__ p)
{
    __shared__ float red[256];
    const long long row = blockIdx.x;
    const float* ps = s + row * (long long)SS;
    __half* pp = p + row * (long long)SS;
    const int tid = threadIdx.x;

    float v[16];
    float mx = -1e30f;
#pragma unroll
    for (int i = 0; i < 4; i++) {
        float4 t = ((const float4*)ps)[tid * 4 + i];
        v[4*i+0] = t.x; v[4*i+1] = t.y; v[4*i+2] = t.z; v[4*i+3] = t.w;
        mx = fmaxf(fmaxf(mx, fmaxf(t.x, t.y)), fmaxf(t.z, t.w));
    }
    red[tid] = mx;
    __syncthreads();
    for (int w = 128; w > 0; w >>= 1) {
        if (tid < w) red[tid] = fmaxf(red[tid], red[tid + w]);
        __syncthreads();
    }
    mx = red[0];
    __syncthreads();

    float sum = 0.0f;
#pragma unroll
    for (int i = 0; i < 16; i++) {
        v[i] = __expf(v[i] - mx);
        sum += v[i];
    }
    red[tid] = sum;
    __syncthreads();
    for (int w = 128; w > 0; w >>= 1) {
        if (tid < w) red[tid] += red[tid + w];
        __syncthreads();
    }
    const float inv = 1.0f / red[0];

    __half2 h[8];
#pragma unroll
    for (int i = 0; i < 8; i++)
        h[i] = __floats2half2_rn(v[2*i] * inv, v[2*i+1] * inv);
    ((uint4*)pp)[tid * 2]     = *(uint4*)&h[0];
    ((uint4*)pp)[tid * 2 + 1] = *(uint4*)&h[4];
}

// ---------------------------------------------------------------------------
extern "C" void kernel_launch(void* const* d_in, const int* in_sizes, int n_in,
                              void* d_out, int out_size)
{
    const float* x  = (const float*)d_in[0];
    const float* wq = (const float*)d_in[1];
    const float* wk = (const float*)d_in[2];
    const float* wv = (const float*)d_in[3];
    float* out = (float*)d_out;

    __half *qh, *kh, *vt, *p;
    float* s;
    cudaGetSymbolAddress((void**)&qh, g_qh);
    cudaGetSymbolAddress((void**)&kh, g_kh);
    cudaGetSymbolAddress((void**)&vt, g_vt);
    cudaGetSymbolAddress((void**)&s,  g_s);
    cudaGetSymbolAddress((void**)&p,  g_p);

    const long long qkvStride = (long long)SS * DD;
    const long long sStride   = (long long)SS * SS;
    const float scale = 1.0f / sqrtf((float)DD);

    // 1) QKV projections (fp32 in, fp16 out; V transposed)
    {
        dim3 grid(DD / 128, (BB * SS) / 128, 1), blk(256);
        gemm_proj<0><<<grid, blk>>>(x, wq, qh);
        gemm_proj<0><<<grid, blk>>>(x, wk, kh);
        gemm_proj<1><<<grid, blk>>>(x, wv, vt);
    }

    // 2) scores = scale * Q @ K^T  (NT fp16), per batch
    {
        dim3 grid(SS / 128, SS / 128, BB), blk(128);
        gemm_h_nt<<<grid, blk>>>(qh, kh, s, DD, DD, DD, SS,
                                 qkvStride, qkvStride, sStride, scale);
    }

    // 3) softmax rows -> fp16 P
    {
        softmax_h<<<BB * SS, 256>>>(s, p);
    }

    // 4) context = P @ (V^T)^T  (NT fp16: B = Vt, K-major), per batch
    {
        dim3 grid(DD / 128, SS / 128, BB), blk(128);
        gemm_h_nt<<<grid, blk>>>(p, vt, out, SS, SS, SS, DD,
                                 sStride, qkvStride, qkvStride, 1.0f);
    }
}

// round 12
// speedup vs baseline: 3.1307x; 1.2007x over previous
#include <cuda_runtime.h>
#include <cuda_fp16.h>
#include <math.h>
#include <stdint.h>

// Problem dims (fixed)
#define BB 2
#define SS 4096
#define DD 512

// Scratch (device globals: allocation-free rule)
__device__ __align__(256) __half g_qh[(size_t)BB * SS * DD];   // Q [b][s][d] fp16
__device__ __align__(256) __half g_kh[(size_t)BB * SS * DD];   // K [b][s][d] fp16
__device__ __align__(256) __half g_vt[(size_t)BB * DD * SS];   // V^T [b][d][s] fp16
__device__ __align__(256) float  g_s [(size_t)BB * SS * SS];   // scores fp32
__device__ __align__(256) __half g_p [(size_t)BB * SS * SS];   // softmax(P) fp16

__device__ __forceinline__ uint32_t pack2(float lo, float hi) {
    __half2 h = __floats2half2_rn(lo, hi);
    return *(uint32_t*)&h;
}
__device__ __forceinline__ uint32_t smem_u32(const void* p) {
    uint32_t a;
    asm("{ .reg .u64 t; cvta.to.shared.u64 t, %1; cvt.u32.u64 %0, t; }"
        : "=r"(a) : "l"(p));
    return a;
}

#define CPA16(dst, src) \
    asm volatile("cp.async.cg.shared.global [%0], [%1], 16;" \
                 :: "r"(dst), "l"(src) : "memory")
#define CPA_COMMIT() asm volatile("cp.async.commit_group;" ::: "memory")
#define CPA_WAIT2()  asm volatile("cp.async.wait_group 2;" ::: "memory")

// ===========================================================================
// NT fp16-operand GEMM: C(fp32) = alpha * A * B^T
//   A [M,K] row-major fp16 (lda), B [N,K] row-major fp16 (ldb)
// CTA 128x128x32(halves), 128 threads = 4 warps (2x2), warp tile 64x64,
// mma.sync.m16n8k16.f32.f16.f16.f32.
// 4-stage cp.async pipeline (stage = 16KB: A 8KB | B 8KB), mainloop
// unrolled by 4 so every stage index / smem address is compile-time.
// Smem rows: 16 words (half2), 16B-chunk XOR swizzle key=(row>>1)&3;
// fragment loads are [reg+imm], conflict-free (proven round 11).
// Requires K % 128 == 0 (nT % 4 == 0): holds (512, 4096).
// ===========================================================================
__global__ void __launch_bounds__(128, 2)
gemm_h_nt(const __half* __restrict__ A, const __half* __restrict__ B,
          float* __restrict__ C, int K, int lda, int ldb, int ldc,
          long long sA, long long sB, long long sC, float alpha)
{
    extern __shared__ uint32_t sm[];            // 4 stages * 4096 words
    const uint32_t smb = smem_u32(sm);

    A += (long long)blockIdx.z * sA;
    B += (long long)blockIdx.z * sB;
    C += (long long)blockIdx.z * sC;

    const int tid  = threadIdx.x;
    const int lane = tid & 31;
    const int wid  = tid >> 5;
    const int warp_m = wid >> 1;          // 0..1 -> 64-row slab
    const int warp_n = wid & 1;           // 0..1 -> 64-col slab
    const int g   = lane >> 2;            // 0..7
    const int tig = lane & 3;             // 0..3

    const int row0 = blockIdx.y * 128;
    const int col0 = blockIdx.x * 128;

    // Loader: 4 tasks/operand; task -> tile row (idx>>2), 16B chunk (idx&3)
    uint32_t stA[4], stB[4];
    const char* pA[4];
    const char* pB[4];
#pragma unroll
    for (int i = 0; i < 4; i++) {
        int idx = tid + i * 128;
        int r = idx >> 2, c = idx & 3;
        uint32_t off = (uint32_t)(r * 16 + ((c ^ ((r >> 1) & 3)) << 2)) * 4u;
        stA[i] = smb + off;
        stB[i] = smb + 8192 + off;
        pA[i] = (const char*)(A + (long long)(row0 + r) * lda + c * 8);
        pB[i] = (const char*)(B + (long long)(col0 + r) * ldb + c * 8);
    }

    // Fragment chunk-base word offsets within a stage (xor key inv. across mt/nt)
    const int lc = (g >> 1) & 3;
    int fa[4], fb[4];
#pragma unroll
    for (int c = 0; c < 4; c++) {
        fa[c] = (warp_m * 64 + g) * 16 + ((c ^ lc) << 2) + tig;
        fb[c] = 2048 + (warp_n * 64 + g) * 16 + ((c ^ lc) << 2) + tig;
    }

    float acc[4][8][4];
#pragma unroll
    for (int mt = 0; mt < 4; mt++)
#pragma unroll
        for (int nt = 0; nt < 8; nt++)
#pragma unroll
            for (int i = 0; i < 4; i++) acc[mt][nt][i] = 0.0f;

    auto FILL = [&](int t, int st) {
        const long long kb = (long long)t * 64;      // 32 halves = 64 B
        const uint32_t so = (uint32_t)st * 16384u;
#pragma unroll
        for (int i = 0; i < 4; i++) CPA16(stA[i] + so, pA[i] + kb);
#pragma unroll
        for (int i = 0; i < 4; i++) CPA16(stB[i] + so, pB[i] + kb);
    };

    auto COMPUTE = [&](int st) {
        const uint32_t* Sb = sm + st * 4096;
#pragma unroll
        for (int s = 0; s < 2; s++) {
            uint32_t af[4][4], bf[8][2];
#pragma unroll
            for (int mt = 0; mt < 4; mt++) {
                af[mt][0] = Sb[fa[2*s]     + mt * 256];
                af[mt][1] = Sb[fa[2*s]     + mt * 256 + 128];
                af[mt][2] = Sb[fa[2*s + 1] + mt * 256];
                af[mt][3] = Sb[fa[2*s + 1] + mt * 256 + 128];
            }
#pragma unroll
            for (int nt = 0; nt < 8; nt++) {
                bf[nt][0] = Sb[fb[2*s]     + nt * 128];
                bf[nt][1] = Sb[fb[2*s + 1] + nt * 128];
            }
#pragma unroll
            for (int nt = 0; nt < 8; nt++)
#pragma unroll
                for (int mt = 0; mt < 4; mt++) {
                    asm volatile(
                        "mma.sync.aligned.m16n8k16.row.col.f32.f16.f16.f32 "
                        "{%0,%1,%2,%3}, {%4,%5,%6,%7}, {%8,%9}, {%0,%1,%2,%3};"
                        : "+f"(acc[mt][nt][0]), "+f"(acc[mt][nt][1]),
                          "+f"(acc[mt][nt][2]), "+f"(acc[mt][nt][3])
                        : "r"(af[mt][0]), "r"(af[mt][1]),
                          "r"(af[mt][2]), "r"(af[mt][3]),
                          "r"(bf[nt][0]), "r"(bf[nt][1]));
                }
        }
    };

    const int nT = K / 32;                // divisible by 4 for our shapes
    FILL(0, 0); CPA_COMMIT();
    FILL(1, 1); CPA_COMMIT();
    FILL(2, 2); CPA_COMMIT();

    for (int t0 = 0; t0 < nT; t0 += 4) {
#pragma unroll
        for (int u = 0; u < 4; u++) {
            const int t = t0 + u;
            CPA_WAIT2();                  // group t complete
            __syncthreads();
            if (t + 3 < nT) FILL(t + 3, (u + 3) & 3);
            CPA_COMMIT();
            COMPUTE(u);
        }
    }

    // Epilogue (fp32)
#pragma unroll
    for (int mt = 0; mt < 4; mt++) {
        const int r = row0 + warp_m * 64 + mt * 16 + g;
#pragma unroll
        for (int nt = 0; nt < 8; nt++) {
            const int c = col0 + warp_n * 64 + nt * 8 + tig * 2;
            float2 v0, v1;
            v0.x = acc[mt][nt][0] * alpha; v0.y = acc[mt][nt][1] * alpha;
            v1.x = acc[mt][nt][2] * alpha; v1.y = acc[mt][nt][3] * alpha;
            *(float2*)&C[(long long)r * ldc + c]       = v0;
            *(float2*)&C[(long long)(r + 8) * ldc + c] = v1;
        }
    }
}

// ===========================================================================
// Projection GEMM (fp32 in, fp16 out): C = A[8192,512] @ B[512,512]
//   OMODE 0: C half [r][c] (ldc=DD)
//   OMODE 1: C half transposed per batch: vt[b][c][s]
// ===========================================================================
#define AW 20
#define BWNN 136

template <int OMODE>
__global__ void __launch_bounds__(256, 2)
gemm_proj(const float* __restrict__ A, const float* __restrict__ B,
          __half* __restrict__ C)
{
    __shared__ uint32_t As[128 * AW];
    __shared__ uint32_t Bs[16 * BWNN];

    const int tid  = threadIdx.x;
    const int lane = tid & 31;
    const int wid  = tid >> 5;
    const int warp_m = wid >> 2;
    const int warp_n = wid & 3;
    const int g   = lane >> 2;
    const int tig = lane & 3;
    const int row0 = blockIdx.y * 128;
    const int col0 = blockIdx.x * 128;

    int a_r[4], a_cf[4], a_cw[4];
#pragma unroll
    for (int i = 0; i < 4; i++) {
        int idx = tid + i * 256;
        a_r[i]  = idx >> 3;
        a_cf[i] = (idx & 7) * 4;
        a_cw[i] = (idx & 7) * 2;
    }
    int b_j[2], b_n4[2];
#pragma unroll
    for (int i = 0; i < 2; i++) {
        int idx = tid + i * 256;
        b_j[i]  = idx >> 5;
        b_n4[i] = (idx & 31) * 4;
    }

    float4 ra[4], rb[4];
    float acc[4][4][4];
#pragma unroll
    for (int mt = 0; mt < 4; mt++)
#pragma unroll
        for (int nt = 0; nt < 4; nt++)
#pragma unroll
            for (int i = 0; i < 4; i++) acc[mt][nt][i] = 0.0f;

    auto LOAD = [&](int k0) {
#pragma unroll
        for (int i = 0; i < 4; i++)
            ra[i] = *(const float4*)&A[(long long)(row0 + a_r[i]) * DD + k0 + a_cf[i]];
#pragma unroll
        for (int i = 0; i < 2; i++) {
            rb[2*i]   = *(const float4*)&B[(long long)(k0 + 2*b_j[i])     * DD + col0 + b_n4[i]];
            rb[2*i+1] = *(const float4*)&B[(long long)(k0 + 2*b_j[i] + 1) * DD + col0 + b_n4[i]];
        }
    };
    auto STORE = [&]() {
#pragma unroll
        for (int i = 0; i < 4; i++) {
            uint2 w;
            w.x = pack2(ra[i].x, ra[i].y);
            w.y = pack2(ra[i].z, ra[i].w);
            *(uint2*)&As[a_r[i] * AW + a_cw[i]] = w;
        }
#pragma unroll
        for (int i = 0; i < 2; i++) {
            uint4 w;
            w.x = pack2(rb[2*i].x, rb[2*i+1].x);
            w.y = pack2(rb[2*i].y, rb[2*i+1].y);
            w.z = pack2(rb[2*i].z, rb[2*i+1].z);
            w.w = pack2(rb[2*i].w, rb[2*i+1].w);
            *(uint4*)&Bs[b_j[i] * BWNN + b_n4[i]] = w;
        }
    };
    auto COMPUTE = [&]() {
#pragma unroll
        for (int s = 0; s < 2; s++) {
            const int c0 = s * 8;
            uint32_t af[4][4];
#pragma unroll
            for (int mt = 0; mt < 4; mt++) {
                const int m = warp_m * 64 + mt * 16;
                af[mt][0] = As[(m + g)     * AW + c0 + tig];
                af[mt][1] = As[(m + g + 8) * AW + c0 + tig];
                af[mt][2] = As[(m + g)     * AW + c0 + tig + 4];
                af[mt][3] = As[(m + g + 8) * AW + c0 + tig + 4];
            }
#pragma unroll
            for (int nt = 0; nt < 4; nt++) {
                const int nb = warp_n * 32 + nt * 8;
                uint32_t b0 = Bs[(c0 + tig)     * BWNN + nb + g];
                uint32_t b1 = Bs[(c0 + tig + 4) * BWNN + nb + g];
#pragma unroll
                for (int mt = 0; mt < 4; mt++) {
                    asm volatile(
                        "mma.sync.aligned.m16n8k16.row.col.f32.f16.f16.f32 "
                        "{%0,%1,%2,%3}, {%4,%5,%6,%7}, {%8,%9}, {%0,%1,%2,%3};"
                        : "+f"(acc[mt][nt][0]), "+f"(acc[mt][nt][1]),
                          "+f"(acc[mt][nt][2]), "+f"(acc[mt][nt][3])
                        : "r"(af[mt][0]), "r"(af[mt][1]),
                          "r"(af[mt][2]), "r"(af[mt][3]),
                          "r"(b0), "r"(b1));
                }
            }
        }
    };

    const int nT = DD / 32;
    LOAD(0);
    STORE();
    __syncthreads();
    for (int t = 1; t < nT; t++) {
        LOAD(t * 32);
        COMPUTE();
        __syncthreads();
        STORE();
        __syncthreads();
    }
    COMPUTE();

#pragma unroll
    for (int mt = 0; mt < 4; mt++) {
        const int r = row0 + warp_m * 64 + mt * 16 + g;
#pragma unroll
        for (int nt = 0; nt < 4; nt++) {
            const int c = col0 + warp_n * 32 + nt * 8 + tig * 2;
            if (OMODE == 0) {
                *(__half2*)&C[(long long)r * DD + c] =
                    __floats2half2_rn(acc[mt][nt][0], acc[mt][nt][1]);
                *(__half2*)&C[(long long)(r + 8) * DD + c] =
                    __floats2half2_rn(acc[mt][nt][2], acc[mt][nt][3]);
            } else {
                const int b  = r >> 12;
                const int sr = r & (SS - 1);
                __half* base = C + (long long)b * DD * SS;
                base[(long long)(c)     * SS + sr]     = __float2half_rn(acc[mt][nt][0]);
                base[(long long)(c + 1) * SS + sr]     = __float2half_rn(acc[mt][nt][1]);
                base[(long long)(c)     * SS + sr + 8] = __float2half_rn(acc[mt][nt][2]);
                base[(long long)(c + 1) * SS + sr + 8] = __float2half_rn(acc[mt][nt][3]);
            }
        }
    }
}

// ---------------------------------------------------------------------------
// Row softmax: fp32 scores in, fp16 P out. 16 consecutive elems per thread.
// ---------------------------------------------------------------------------
__global__ void __launch_bounds__(256)
softmax_h(const float* __restrict__ s, __half* __restrict__ p)
{
    __shared__ float red[256];
    const long long row = blockIdx.x;
    const float* ps = s + row * (long long)SS;
    __half* pp = p + row * (long long)SS;
    const int tid = threadIdx.x;

    float v[16];
    float mx = -1e30f;
#pragma unroll
    for (int i = 0; i < 4; i++) {
        float4 t = ((const float4*)ps)[tid * 4 + i];
        v[4*i+0] = t.x; v[4*i+1] = t.y; v[4*i+2] = t.z; v[4*i+3] = t.w;
        mx = fmaxf(fmaxf(mx, fmaxf(t.x, t.y)), fmaxf(t.z, t.w));
    }
    red[tid] = mx;
    __syncthreads();
    for (int w = 128; w > 0; w >>= 1) {
        if (tid < w) red[tid] = fmaxf(red[tid], red[tid + w]);
        __syncthreads();
    }
    mx = red[0];
    __syncthreads();

    float sum = 0.0f;
#pragma unroll
    for (int i = 0; i < 16; i++) {
        v[i] = __expf(v[i] - mx);
        sum += v[i];
    }
    red[tid] = sum;
    __syncthreads();
    for (int w = 128; w > 0; w >>= 1) {
        if (tid < w) red[tid] += red[tid + w];
        __syncthreads();
    }
    const float inv = 1.0f / red[0];

    __half2 h[8];
#pragma unroll
    for (int i = 0; i < 8; i++)
        h[i] = __floats2half2_rn(v[2*i] * inv, v[2*i+1] * inv);
    ((uint4*)pp)[tid * 2]     = *(uint4*)&h[0];
    ((uint4*)pp)[tid * 2 + 1] = *(uint4*)&h[4];
}

// ---------------------------------------------------------------------------
extern "C" void kernel_launch(void* const* d_in, const int* in_sizes, int n_in,
                              void* d_out, int out_size)
{
    const float* x  = (const float*)d_in[0];
    const float* wq = (const float*)d_in[1];
    const float* wk = (const float*)d_in[2];
    const float* wv = (const float*)d_in[3];
    float* out = (float*)d_out;

    __half *qh, *kh, *vt, *p;
    float* s;
    cudaGetSymbolAddress((void**)&qh, g_qh);
    cudaGetSymbolAddress((void**)&kh, g_kh);
    cudaGetSymbolAddress((void**)&vt, g_vt);
    cudaGetSymbolAddress((void**)&s,  g_s);
    cudaGetSymbolAddress((void**)&p,  g_p);

    const long long qkvStride = (long long)SS * DD;
    const long long sStride   = (long long)SS * SS;
    const float scale = 1.0f / sqrtf((float)DD);
    const int smemBytes = 4 * 16384;   // 4-stage pipeline

    cudaFuncSetAttribute(gemm_h_nt,
                         cudaFuncAttributeMaxDynamicSharedMemorySize, smemBytes);

    // 1) QKV projections (fp32 in, fp16 out; V transposed)
    {
        dim3 grid(DD / 128, (BB * SS) / 128, 1), blk(256);
        gemm_proj<0><<<grid, blk>>>(x, wq, qh);
        gemm_proj<0><<<grid, blk>>>(x, wk, kh);
        gemm_proj<1><<<grid, blk>>>(x, wv, vt);
    }

    // 2) scores = scale * Q @ K^T  (NT fp16), per batch
    {
        dim3 grid(SS / 128, SS / 128, BB), blk(128);
        gemm_h_nt<<<grid, blk, smemBytes>>>(qh, kh, s, DD, DD, DD, SS,
                                            qkvStride, qkvStride, sStride, scale);
    }

    // 3) softmax rows -> fp16 P
    {
        softmax_h<<<BB * SS, 256>>>(s, p);
    }

    // 4) context = P @ (V^T)^T  (NT fp16: B = Vt, K-major), per batch
    {
        dim3 grid(DD / 128, SS / 128, BB), blk(128);
        gemm_h_nt<<<grid, blk, smemBytes>>>(p, vt, out, SS, SS, SS, DD,
                                            sStride, qkvStride, qkvStride, 1.0f);
    }
}

// round 13
// speedup vs baseline: 3.5239x; 1.1256x over previous
#include <cuda_runtime.h>
#include <cuda_fp16.h>
#include <math.h>
#include <stdint.h>

// Problem dims (fixed)
#define BB 2
#define SS 4096
#define DD 512

// Scratch (device globals: allocation-free rule)
__device__ __align__(256) __half g_qh[(size_t)BB * SS * DD];   // Q [b][s][d] fp16
__device__ __align__(256) __half g_kh[(size_t)BB * SS * DD];   // K [b][s][d] fp16
__device__ __align__(256) __half g_vt[(size_t)BB * DD * SS];   // V^T [b][d][s] fp16
__device__ __align__(256) __half g_p [(size_t)BB * SS * SS];   // unnormalized exp(S) fp16
__device__ __align__(256) float  g_part[(size_t)BB * SS * 64]; // per-(row, colslab) partial sums
__device__ __align__(256) float  g_rsum[(size_t)BB * SS];      // 1 / rowsum

__device__ __forceinline__ uint32_t pack2(float lo, float hi) {
    __half2 h = __floats2half2_rn(lo, hi);
    return *(uint32_t*)&h;
}
__device__ __forceinline__ uint32_t smem_u32(const void* p) {
    uint32_t a;
    asm("{ .reg .u64 t; cvta.to.shared.u64 t, %1; cvt.u32.u64 %0, t; }"
        : "=r"(a) : "l"(p));
    return a;
}

#define CPA16(dst, src) \
    asm volatile("cp.async.cg.shared.global [%0], [%1], 16;" \
                 :: "r"(dst), "l"(src) : "memory")
#define CPA_COMMIT() asm volatile("cp.async.commit_group;" ::: "memory")
#define CPA_WAIT2()  asm volatile("cp.async.wait_group 2;" ::: "memory")

// ===========================================================================
// NT fp16-operand GEMM, 4-stage cp.async pipeline (proven round 12).
// MODE 0 (QK): epilogue computes e = expf(scale*acc), stores fp16 P
//              (unnormalized), and writes deterministic partial row sums
//              to part[row][bx*2+warp_n].
// MODE 1 (PV): epilogue stores fp32 C scaled by rsum_inv[row].
// CTA 128x128x32(halves), 128 threads = 4 warps (2x2), warp tile 64x64.
// ===========================================================================
template <int MODE>
__global__ void __launch_bounds__(128, 2)
gemm_h_nt(const __half* __restrict__ A, const __half* __restrict__ B,
          float* __restrict__ Cf, __half* __restrict__ Ch,
          float* __restrict__ part, const float* __restrict__ rsum,
          int K, int lda, int ldb, int ldc,
          long long sA, long long sB, long long sC, float alpha)
{
    extern __shared__ uint32_t sm[];            // 4 stages * 4096 words
    const uint32_t smb = smem_u32(sm);

    A += (long long)blockIdx.z * sA;
    B += (long long)blockIdx.z * sB;

    const int tid  = threadIdx.x;
    const int lane = tid & 31;
    const int wid  = tid >> 5;
    const int warp_m = wid >> 1;
    const int warp_n = wid & 1;
    const int g   = lane >> 2;
    const int tig = lane & 3;

    const int row0 = blockIdx.y * 128;
    const int col0 = blockIdx.x * 128;
    const long long zrow = (long long)blockIdx.z * SS;

    uint32_t stA[4], stB[4];
    const char* pA[4];
    const char* pB[4];
#pragma unroll
    for (int i = 0; i < 4; i++) {
        int idx = tid + i * 128;
        int r = idx >> 2, c = idx & 3;
        uint32_t off = (uint32_t)(r * 16 + ((c ^ ((r >> 1) & 3)) << 2)) * 4u;
        stA[i] = smb + off;
        stB[i] = smb + 8192 + off;
        pA[i] = (const char*)(A + (long long)(row0 + r) * lda + c * 8);
        pB[i] = (const char*)(B + (long long)(col0 + r) * ldb + c * 8);
    }

    const int lc = (g >> 1) & 3;
    int fa[4], fb[4];
#pragma unroll
    for (int c = 0; c < 4; c++) {
        fa[c] = (warp_m * 64 + g) * 16 + ((c ^ lc) << 2) + tig;
        fb[c] = 2048 + (warp_n * 64 + g) * 16 + ((c ^ lc) << 2) + tig;
    }

    float acc[4][8][4];
#pragma unroll
    for (int mt = 0; mt < 4; mt++)
#pragma unroll
        for (int nt = 0; nt < 8; nt++)
#pragma unroll
            for (int i = 0; i < 4; i++) acc[mt][nt][i] = 0.0f;

    auto FILL = [&](int t, int st) {
        const long long kb = (long long)t * 64;
        const uint32_t so = (uint32_t)st * 16384u;
#pragma unroll
        for (int i = 0; i < 4; i++) CPA16(stA[i] + so, pA[i] + kb);
#pragma unroll
        for (int i = 0; i < 4; i++) CPA16(stB[i] + so, pB[i] + kb);
    };

    auto COMPUTE = [&](int st) {
        const uint32_t* Sb = sm + st * 4096;
#pragma unroll
        for (int s = 0; s < 2; s++) {
            uint32_t af[4][4], bf[8][2];
#pragma unroll
            for (int mt = 0; mt < 4; mt++) {
                af[mt][0] = Sb[fa[2*s]     + mt * 256];
                af[mt][1] = Sb[fa[2*s]     + mt * 256 + 128];
                af[mt][2] = Sb[fa[2*s + 1] + mt * 256];
                af[mt][3] = Sb[fa[2*s + 1] + mt * 256 + 128];
            }
#pragma unroll
            for (int nt = 0; nt < 8; nt++) {
                bf[nt][0] = Sb[fb[2*s]     + nt * 128];
                bf[nt][1] = Sb[fb[2*s + 1] + nt * 128];
            }
#pragma unroll
            for (int nt = 0; nt < 8; nt++)
#pragma unroll
                for (int mt = 0; mt < 4; mt++) {
                    asm volatile(
                        "mma.sync.aligned.m16n8k16.row.col.f32.f16.f16.f32 "
                        "{%0,%1,%2,%3}, {%4,%5,%6,%7}, {%8,%9}, {%0,%1,%2,%3};"
                        : "+f"(acc[mt][nt][0]), "+f"(acc[mt][nt][1]),
                          "+f"(acc[mt][nt][2]), "+f"(acc[mt][nt][3])
                        : "r"(af[mt][0]), "r"(af[mt][1]),
                          "r"(af[mt][2]), "r"(af[mt][3]),
                          "r"(bf[nt][0]), "r"(bf[nt][1]));
                }
        }
    };

    const int nT = K / 32;                // divisible by 4 for our shapes
    FILL(0, 0); CPA_COMMIT();
    FILL(1, 1); CPA_COMMIT();
    FILL(2, 2); CPA_COMMIT();

    for (int t0 = 0; t0 < nT; t0 += 4) {
#pragma unroll
        for (int u = 0; u < 4; u++) {
            const int t = t0 + u;
            CPA_WAIT2();
            __syncthreads();
            if (t + 3 < nT) FILL(t + 3, (u + 3) & 3);
            CPA_COMMIT();
            COMPUTE(u);
        }
    }

    if (MODE == 0) {
        // exp epilogue: P (fp16, unnormalized) + deterministic partial sums
        Ch += zrow * SS;
#pragma unroll
        for (int mt = 0; mt < 4; mt++) {
            const int r = row0 + warp_m * 64 + mt * 16 + g;
            float s0 = 0.0f, s1 = 0.0f;
#pragma unroll
            for (int nt = 0; nt < 8; nt++) {
                const int c = col0 + warp_n * 64 + nt * 8 + tig * 2;
                float e0 = __expf(acc[mt][nt][0] * alpha);
                float e1 = __expf(acc[mt][nt][1] * alpha);
                float e2 = __expf(acc[mt][nt][2] * alpha);
                float e3 = __expf(acc[mt][nt][3] * alpha);
                s0 += e0 + e1;
                s1 += e2 + e3;
                *(__half2*)&Ch[(long long)r * ldc + c]       = __floats2half2_rn(e0, e1);
                *(__half2*)&Ch[(long long)(r + 8) * ldc + c] = __floats2half2_rn(e2, e3);
            }
            // reduce over the 4 tig lanes (same row, different columns)
            s0 += __shfl_xor_sync(0xFFFFFFFF, s0, 1);
            s0 += __shfl_xor_sync(0xFFFFFFFF, s0, 2);
            s1 += __shfl_xor_sync(0xFFFFFFFF, s1, 1);
            s1 += __shfl_xor_sync(0xFFFFFFFF, s1, 2);
            if (tig == 0) {
                const int slot = blockIdx.x * 2 + warp_n;
                part[(zrow + r)     * 64 + slot] = s0;
                part[(zrow + r + 8) * 64 + slot] = s1;
            }
        }
    } else {
        // normalize epilogue: C = acc * rsum_inv[row]
        Cf += zrow * DD;
#pragma unroll
        for (int mt = 0; mt < 4; mt++) {
            const int r = row0 + warp_m * 64 + mt * 16 + g;
            const float inv0 = rsum[zrow + r];
            const float inv1 = rsum[zrow + r + 8];
#pragma unroll
            for (int nt = 0; nt < 8; nt++) {
                const int c = col0 + warp_n * 64 + nt * 8 + tig * 2;
                float2 v0, v1;
                v0.x = acc[mt][nt][0] * inv0; v0.y = acc[mt][nt][1] * inv0;
                v1.x = acc[mt][nt][2] * inv1; v1.y = acc[mt][nt][3] * inv1;
                *(float2*)&Cf[(long long)r * ldc + c]       = v0;
                *(float2*)&Cf[(long long)(r + 8) * ldc + c] = v1;
            }
        }
    }
}

// ---------------------------------------------------------------------------
// rowsum reduce: rsum_inv[row] = 1 / sum(part[row][0..63]).  8 warps/block,
// one warp per row, deterministic.
// ---------------------------------------------------------------------------
__global__ void __launch_bounds__(256)
rowsum_inv(const float* __restrict__ part, float* __restrict__ rsum)
{
    const int row  = blockIdx.x * 8 + (threadIdx.x >> 5);
    const int lane = threadIdx.x & 31;
    const float* p = part + (long long)row * 64;
    float v = p[lane] + p[lane + 32];
#pragma unroll
    for (int o = 16; o > 0; o >>= 1)
        v += __shfl_xor_sync(0xFFFFFFFF, v, o);
    if (lane == 0) rsum[row] = 1.0f / v;
}

// ===========================================================================
// Projection GEMM (fp32 in, fp16 out): C = A[8192,512] @ B[512,512]
//   OMODE 0: C half [r][c] (ldc=DD)
//   OMODE 1: C half transposed per batch: vt[b][c][s]
// ===========================================================================
#define AW 20
#define BWNN 136

template <int OMODE>
__global__ void __launch_bounds__(256, 2)
gemm_proj(const float* __restrict__ A, const float* __restrict__ B,
          __half* __restrict__ C)
{
    __shared__ uint32_t As[128 * AW];
    __shared__ uint32_t Bs[16 * BWNN];

    const int tid  = threadIdx.x;
    const int lane = tid & 31;
    const int wid  = tid >> 5;
    const int warp_m = wid >> 2;
    const int warp_n = wid & 3;
    const int g   = lane >> 2;
    const int tig = lane & 3;
    const int row0 = blockIdx.y * 128;
    const int col0 = blockIdx.x * 128;

    int a_r[4], a_cf[4], a_cw[4];
#pragma unroll
    for (int i = 0; i < 4; i++) {
        int idx = tid + i * 256;
        a_r[i]  = idx >> 3;
        a_cf[i] = (idx & 7) * 4;
        a_cw[i] = (idx & 7) * 2;
    }
    int b_j[2], b_n4[2];
#pragma unroll
    for (int i = 0; i < 2; i++) {
        int idx = tid + i * 256;
        b_j[i]  = idx >> 5;
        b_n4[i] = (idx & 31) * 4;
    }

    float4 ra[4], rb[4];
    float acc[4][4][4];
#pragma unroll
    for (int mt = 0; mt < 4; mt++)
#pragma unroll
        for (int nt = 0; nt < 4; nt++)
#pragma unroll
            for (int i = 0; i < 4; i++) acc[mt][nt][i] = 0.0f;

    auto LOAD = [&](int k0) {
#pragma unroll
        for (int i = 0; i < 4; i++)
            ra[i] = *(const float4*)&A[(long long)(row0 + a_r[i]) * DD + k0 + a_cf[i]];
#pragma unroll
        for (int i = 0; i < 2; i++) {
            rb[2*i]   = *(const float4*)&B[(long long)(k0 + 2*b_j[i])     * DD + col0 + b_n4[i]];
            rb[2*i+1] = *(const float4*)&B[(long long)(k0 + 2*b_j[i] + 1) * DD + col0 + b_n4[i]];
        }
    };
    auto STORE = [&]() {
#pragma unroll
        for (int i = 0; i < 4; i++) {
            uint2 w;
            w.x = pack2(ra[i].x, ra[i].y);
            w.y = pack2(ra[i].z, ra[i].w);
            *(uint2*)&As[a_r[i] * AW + a_cw[i]] = w;
        }
#pragma unroll
        for (int i = 0; i < 2; i++) {
            uint4 w;
            w.x = pack2(rb[2*i].x, rb[2*i+1].x);
            w.y = pack2(rb[2*i].y, rb[2*i+1].y);
            w.z = pack2(rb[2*i].z, rb[2*i+1].z);
            w.w = pack2(rb[2*i].w, rb[2*i+1].w);
            *(uint4*)&Bs[b_j[i] * BWNN + b_n4[i]] = w;
        }
    };
    auto COMPUTE = [&]() {
#pragma unroll
        for (int s = 0; s < 2; s++) {
            const int c0 = s * 8;
            uint32_t af[4][4];
#pragma unroll
            for (int mt = 0; mt < 4; mt++) {
                const int m = warp_m * 64 + mt * 16;
                af[mt][0] = As[(m + g)     * AW + c0 + tig];
                af[mt][1] = As[(m + g + 8) * AW + c0 + tig];
                af[mt][2] = As[(m + g)     * AW + c0 + tig + 4];
                af[mt][3] = As[(m + g + 8) * AW + c0 + tig + 4];
            }
#pragma unroll
            for (int nt = 0; nt < 4; nt++) {
                const int nb = warp_n * 32 + nt * 8;
                uint32_t b0 = Bs[(c0 + tig)     * BWNN + nb + g];
                uint32_t b1 = Bs[(c0 + tig + 4) * BWNN + nb + g];
#pragma unroll
                for (int mt = 0; mt < 4; mt++) {
                    asm volatile(
                        "mma.sync.aligned.m16n8k16.row.col.f32.f16.f16.f32 "
                        "{%0,%1,%2,%3}, {%4,%5,%6,%7}, {%8,%9}, {%0,%1,%2,%3};"
                        : "+f"(acc[mt][nt][0]), "+f"(acc[mt][nt][1]),
                          "+f"(acc[mt][nt][2]), "+f"(acc[mt][nt][3])
                        : "r"(af[mt][0]), "r"(af[mt][1]),
                          "r"(af[mt][2]), "r"(af[mt][3]),
                          "r"(b0), "r"(b1));
                }
            }
        }
    };

    const int nT = DD / 32;
    LOAD(0);
    STORE();
    __syncthreads();
    for (int t = 1; t < nT; t++) {
        LOAD(t * 32);
        COMPUTE();
        __syncthreads();
        STORE();
        __syncthreads();
    }
    COMPUTE();

#pragma unroll
    for (int mt = 0; mt < 4; mt++) {
        const int r = row0 + warp_m * 64 + mt * 16 + g;
#pragma unroll
        for (int nt = 0; nt < 4; nt++) {
            const int c = col0 + warp_n * 32 + nt * 8 + tig * 2;
            if (OMODE == 0) {
                *(__half2*)&C[(long long)r * DD + c] =
                    __floats2half2_rn(acc[mt][nt][0], acc[mt][nt][1]);
                *(__half2*)&C[(long long)(r + 8) * DD + c] =
                    __floats2half2_rn(acc[mt][nt][2], acc[mt][nt][3]);
            } else {
                const int b  = r >> 12;
                const int sr = r & (SS - 1);
                __half* base = C + (long long)b * DD * SS;
                base[(long long)(c)     * SS + sr]     = __float2half_rn(acc[mt][nt][0]);
                base[(long long)(c + 1) * SS + sr]     = __float2half_rn(acc[mt][nt][1]);
                base[(long long)(c)     * SS + sr + 8] = __float2half_rn(acc[mt][nt][2]);
                base[(long long)(c + 1) * SS + sr + 8] = __float2half_rn(acc[mt][nt][3]);
            }
        }
    }
}

// ---------------------------------------------------------------------------
extern "C" void kernel_launch(void* const* d_in, const int* in_sizes, int n_in,
                              void* d_out, int out_size)
{
    const float* x  = (const float*)d_in[0];
    const float* wq = (const float*)d_in[1];
    const float* wk = (const float*)d_in[2];
    const float* wv = (const float*)d_in[3];
    float* out = (float*)d_out;

    __half *qh, *kh, *vt, *p;
    float *part, *rsum;
    cudaGetSymbolAddress((void**)&qh,   g_qh);
    cudaGetSymbolAddress((void**)&kh,   g_kh);
    cudaGetSymbolAddress((void**)&vt,   g_vt);
    cudaGetSymbolAddress((void**)&p,    g_p);
    cudaGetSymbolAddress((void**)&part, g_part);
    cudaGetSymbolAddress((void**)&rsum, g_rsum);

    const long long qkvStride = (long long)SS * DD;
    const long long sStride   = (long long)SS * SS;
    const float scale = 1.0f / sqrtf((float)DD);
    const int smemBytes = 4 * 16384;

    cudaFuncSetAttribute(gemm_h_nt<0>,
                         cudaFuncAttributeMaxDynamicSharedMemorySize, smemBytes);
    cudaFuncSetAttribute(gemm_h_nt<1>,
                         cudaFuncAttributeMaxDynamicSharedMemorySize, smemBytes);

    // 1) QKV projections (fp32 in, fp16 out; V transposed)
    {
        dim3 grid(DD / 128, (BB * SS) / 128, 1), blk(256);
        gemm_proj<0><<<grid, blk>>>(x, wq, qh);
        gemm_proj<0><<<grid, blk>>>(x, wk, kh);
        gemm_proj<1><<<grid, blk>>>(x, wv, vt);
    }

    // 2) P = exp(scale * Q @ K^T) fp16 + partial row sums, per batch
    {
        dim3 grid(SS / 128, SS / 128, BB), blk(128);
        gemm_h_nt<0><<<grid, blk, smemBytes>>>(qh, kh, nullptr, p, part, nullptr,
                                               DD, DD, DD, SS,
                                               qkvStride, qkvStride, sStride, scale);
    }

    // 3) rsum_inv[row] = 1 / sum of 64 partials
    {
        rowsum_inv<<<(BB * SS) / 8, 256>>>(part, rsum);
    }

    // 4) context = (P @ Vt^T) * rsum_inv, per batch
    {
        dim3 grid(DD / 128, SS / 128, BB), blk(128);
        gemm_h_nt<1><<<grid, blk, smemBytes>>>(p, vt, out, nullptr, nullptr, rsum,
                                               SS, SS, SS, DD,
                                               sStride, qkvStride, qkvStride, 1.0f);
    }
}